// round 1
// baseline (speedup 1.0000x reference)
#include <cuda_runtime.h>
#include <math.h>

// Problem constants
#define BB   256      // batch
#define TT   256      // time steps
#define ID   256      // input dim
#define HH   1024     // hidden dim
#define GG   4096     // 4*H gates

typedef unsigned long long ull;

// Scratch (device globals: allocation-free rule)
__device__ float g_pre[(size_t)BB * TT * GG];   // 1 GiB: precomputed input gates
__device__ float g_wf[ID * GG];                 // W with Wy folded into row 255

// ---------------------------------------------------------------------------
// packed f32x2 helpers
// ---------------------------------------------------------------------------
__device__ __forceinline__ ull pk2(float lo, float hi) {
    ull r;
    asm("mov.b64 %0, {%1, %2};" : "=l"(r) : "f"(lo), "f"(hi));
    return r;
}
__device__ __forceinline__ void upk2(ull v, float& lo, float& hi) {
    asm("mov.b64 {%0, %1}, %2;" : "=f"(lo), "=f"(hi) : "l"(v));
}
__device__ __forceinline__ ull ffma2(ull a, ull b, ull c) {
    ull d;
    asm("fma.rn.f32x2 %0, %1, %2, %3;" : "=l"(d) : "l"(a), "l"(b), "l"(c));
    return d;
}

__device__ __forceinline__ float sigmoidf_(float x) {
    return 1.0f / (1.0f + expf(-x));
}

// ---------------------------------------------------------------------------
// Kernel 1: fold Wy into W row 255  (pre = X@W + X[:,:,255]*Wy + bias)
// ---------------------------------------------------------------------------
__global__ void fold_w_kernel(const float* __restrict__ W,
                              const float* __restrict__ Wy) {
    int idx = blockIdx.x * blockDim.x + threadIdx.x;   // 0 .. ID*GG-1
    int d = idx >> 12;            // /4096
    int g = idx & (GG - 1);
    float v = W[idx];
    if (d == ID - 1) v += Wy[g];
    g_wf[idx] = v;
}

// ---------------------------------------------------------------------------
// Kernel 2: pre[m, g] = X[m, :] @ Wf + bias[g],  M = B*T = 65536, K = 256
// 128x128 tile, BK=16, 256 threads, 8x8 per thread, fp32
// ---------------------------------------------------------------------------
__global__ __launch_bounds__(256) void pre_gemm_kernel(
    const float* __restrict__ X, const float* __restrict__ bias) {
    __shared__ float As[16][132];   // [k][m], padded
    __shared__ float Bs[16][128];   // [k][n]

    const int tid = threadIdx.x;
    const int tx = tid & 15;        // n dir (8 cols)
    const int ty = tid >> 4;        // m dir (8 rows)
    const int nb = blockIdx.x;      // 0..31
    const int mb = blockIdx.y;      // 0..511

    float acc[8][8];
#pragma unroll
    for (int i = 0; i < 8; ++i)
#pragma unroll
        for (int j = 0; j < 8; ++j) acc[i][j] = 0.f;

    for (int kb = 0; kb < ID / 16; ++kb) {
        const int k0 = kb * 16;
        // load A tile: 128 rows x 16 k  (2 float4 per thread)
#pragma unroll
        for (int i = 0; i < 2; ++i) {
            int a_i = tid * 2 + i;
            int r = a_i >> 2;
            int kq = a_i & 3;
            float4 v = *(const float4*)(X + (size_t)(mb * 128 + r) * ID + k0 + kq * 4);
            As[kq * 4 + 0][r] = v.x;
            As[kq * 4 + 1][r] = v.y;
            As[kq * 4 + 2][r] = v.z;
            As[kq * 4 + 3][r] = v.w;
        }
        // load B tile: 16 k x 128 n (2 float4 per thread)
#pragma unroll
        for (int i = 0; i < 2; ++i) {
            int b_i = tid * 2 + i;
            int kk = b_i >> 5;
            int nq = b_i & 31;
            float4 v = *(const float4*)(g_wf + (size_t)(k0 + kk) * GG + nb * 128 + nq * 4);
            *(float4*)&Bs[kk][nq * 4] = v;
        }
        __syncthreads();
#pragma unroll
        for (int kk = 0; kk < 16; ++kk) {
            float a[8], b[8];
            *(float4*)&a[0] = *(const float4*)&As[kk][ty * 8];
            *(float4*)&a[4] = *(const float4*)&As[kk][ty * 8 + 4];
            *(float4*)&b[0] = *(const float4*)&Bs[kk][tx * 8];
            *(float4*)&b[4] = *(const float4*)&Bs[kk][tx * 8 + 4];
#pragma unroll
            for (int i = 0; i < 8; ++i)
#pragma unroll
                for (int j = 0; j < 8; ++j) acc[i][j] += a[i] * b[j];
        }
        __syncthreads();
    }

    // epilogue: add bias, store
    const int ncol = nb * 128 + tx * 8;
    float bb0[8];
#pragma unroll
    for (int j = 0; j < 8; ++j) bb0[j] = bias[ncol + j];
#pragma unroll
    for (int i = 0; i < 8; ++i) {
        size_t row = (size_t)mb * 128 + ty * 8 + i;
        float4 o0, o1;
        o0.x = acc[i][0] + bb0[0]; o0.y = acc[i][1] + bb0[1];
        o0.z = acc[i][2] + bb0[2]; o0.w = acc[i][3] + bb0[3];
        o1.x = acc[i][4] + bb0[4]; o1.y = acc[i][5] + bb0[5];
        o1.z = acc[i][6] + bb0[6]; o1.w = acc[i][7] + bb0[7];
        *(float4*)(g_pre + row * GG + ncol) = o0;
        *(float4*)(g_pre + row * GG + ncol + 4) = o1;
    }
}

// ---------------------------------------------------------------------------
// Kernel 3: one LSTM step.
// gates[b, :] = pre[b, t, :] + h_{t-1}[b, :] @ U    then cell update.
// Tile: 64 rows (batch) x 32 hidden-j, all 4 gates per thread (full fusion).
// grid (32, 4), 256 threads. FFMA2-packed over the j-pair.
// ---------------------------------------------------------------------------
__global__ __launch_bounds__(256) void lstm_step_kernel(
    const float* __restrict__ U,
    float* __restrict__ hidden,      // [B][T][H]
    float* __restrict__ c_state,     // [B][H]
    float* __restrict__ h_final,     // [B][H]
    int t) {
    __shared__ float As[16][68];      // h_prev tile, [k][row], padded
    __shared__ float Us[16][4][32];   // U tile: [k][gate][j]

    const int tid = threadIdx.x;
    const int tx = tid & 15;          // j dir: 2 j's
    const int ty = tid >> 4;          // row dir: 4 rows
    const int jb = blockIdx.x;        // 0..31
    const int rb = blockIdx.y;        // 0..3

    ull acc[4][4];                    // [row][gate], packed j-pair
#pragma unroll
    for (int m = 0; m < 4; ++m)
#pragma unroll
        for (int g = 0; g < 4; ++g) acc[m][g] = 0ull;

    if (t > 0) {
        const int lr = tid >> 2;      // 0..63 A-load row
        const int lkq = tid & 3;
        const int lkk = tid >> 4;     // U-load k row
        const int lu = tid & 15;
        for (int kb = 0; kb < HH / 16; ++kb) {
            const int k0 = kb * 16;
            {   // A: h_{t-1}[rb*64 + lr, k0 + lkq*4 .. +3]
                int b = rb * 64 + lr;
                float4 v = *(const float4*)(hidden + ((size_t)b * TT + (t - 1)) * HH + k0 + lkq * 4);
                As[lkq * 4 + 0][lr] = v.x;
                As[lkq * 4 + 1][lr] = v.y;
                As[lkq * 4 + 2][lr] = v.z;
                As[lkq * 4 + 3][lr] = v.w;
            }
            {   // U: 16k x (4 gates x 32 j)
                const float* Urow = U + (size_t)(k0 + lkk) * GG + jb * 32;
#pragma unroll
                for (int h = 0; h < 2; ++h) {
                    int v = lu + h * 16;
                    int gate = v >> 3;
                    int jj = (v & 7) * 4;
                    float4 w = *(const float4*)(Urow + gate * HH + jj);
                    *(float4*)&Us[lkk][gate][jj] = w;
                }
            }
            __syncthreads();
#pragma unroll
            for (int kk = 0; kk < 16; ++kk) {
                float4 a4 = *(const float4*)&As[kk][ty * 4];
                ull ap0 = pk2(a4.x, a4.x);
                ull ap1 = pk2(a4.y, a4.y);
                ull ap2 = pk2(a4.z, a4.z);
                ull ap3 = pk2(a4.w, a4.w);
#pragma unroll
                for (int gg = 0; gg < 4; ++gg) {
                    ull u2 = *(const ull*)&Us[kk][gg][tx * 2];
                    acc[0][gg] = ffma2(ap0, u2, acc[0][gg]);
                    acc[1][gg] = ffma2(ap1, u2, acc[1][gg]);
                    acc[2][gg] = ffma2(ap2, u2, acc[2][gg]);
                    acc[3][gg] = ffma2(ap3, u2, acc[3][gg]);
                }
            }
            __syncthreads();
        }
    }

    // epilogue: gates -> cell update
    const int j0 = jb * 32 + tx * 2;
#pragma unroll
    for (int m = 0; m < 4; ++m) {
        int b = rb * 64 + ty * 4 + m;
        const float* prow = g_pre + ((size_t)b * TT + t) * GG;
        float glo[4], ghi[4];
#pragma unroll
        for (int gg = 0; gg < 4; ++gg) upk2(acc[m][gg], glo[gg], ghi[gg]);
#pragma unroll
        for (int s = 0; s < 2; ++s) {
            int j = j0 + s;
            float gi = (s ? ghi[0] : glo[0]) + prow[0 * HH + j];
            float gf = (s ? ghi[1] : glo[1]) + prow[1 * HH + j];
            float gc = (s ? ghi[2] : glo[2]) + prow[2 * HH + j];
            float go = (s ? ghi[3] : glo[3]) + prow[3 * HH + j];
            float iv = sigmoidf_(gi);
            float fv = sigmoidf_(gf);
            float cv = tanhf(gc);
            float ov = sigmoidf_(go);
            float cold = (t > 0) ? c_state[b * HH + j] : 0.f;
            float cn = fv * cold + iv * cv;
            float hn = ov * tanhf(cn);
            c_state[b * HH + j] = cn;
            hidden[(size_t)b * TT * HH + (size_t)t * HH + j] = hn;
            if (t == TT - 1) h_final[b * HH + j] = hn;
        }
    }
}

// ---------------------------------------------------------------------------
// Kernel 4: y_pred[b] = h_final[b,:] . fc_w + fc_b
// ---------------------------------------------------------------------------
__global__ void fc_kernel(const float* __restrict__ h_final,
                          const float* __restrict__ fc_w,
                          const float* __restrict__ fc_b,
                          float* __restrict__ y_pred) {
    int b = blockIdx.x;
    int tid = threadIdx.x;   // 256
    float s = 0.f;
    for (int k = tid; k < HH; k += 256)
        s += h_final[b * HH + k] * fc_w[k];
#pragma unroll
    for (int off = 16; off > 0; off >>= 1)
        s += __shfl_down_sync(0xffffffffu, s, off);
    __shared__ float red[8];
    if ((tid & 31) == 0) red[tid >> 5] = s;
    __syncthreads();
    if (tid == 0) {
        float tot = 0.f;
#pragma unroll
        for (int w = 0; w < 8; ++w) tot += red[w];
        y_pred[b] = tot + fc_b[0];
    }
}

// ---------------------------------------------------------------------------
extern "C" void kernel_launch(void* const* d_in, const int* in_sizes, int n_in,
                              void* d_out, int out_size) {
    const float* X    = (const float*)d_in[0];
    const float* W    = (const float*)d_in[1];
    const float* U    = (const float*)d_in[2];
    const float* bias = (const float*)d_in[3];
    const float* Wy   = (const float*)d_in[4];
    const float* fc_w = (const float*)d_in[5];
    const float* fc_b = (const float*)d_in[6];

    float* out = (float*)d_out;
    // output layout: y_pred[256] | hidden_seq[B*T*H] | h_t[B*H] | c_t[B*H]
    float* y_pred  = out;
    float* hidden  = out + 256;
    float* h_final = hidden + (size_t)BB * TT * HH;
    float* c_state = h_final + (size_t)BB * HH;

    fold_w_kernel<<<1024, 1024>>>(W, Wy);
    pre_gemm_kernel<<<dim3(GG / 128, (BB * TT) / 128), 256>>>(X, bias);
    for (int t = 0; t < TT; ++t)
        lstm_step_kernel<<<dim3(HH / 32, BB / 64), 256>>>(U, hidden, c_state, h_final, t);
    fc_kernel<<<BB, 256>>>(h_final, fc_w, fc_b, y_pred);
}